// round 14
// baseline (speedup 1.0000x reference)
#include <cuda_runtime.h>
#include <math.h>

#define H 1024
#define W 1024
#define NB 32
#define NPIX (1024*1024)
#define SEGS 8
#define SEGH 128

// Scratch (allocation is forbidden; use device globals)
__device__ float g_x1[33554432];
__device__ float g_i2top[NB * 32 * 3 * W];   // seg-local i2 at rows 32k..32k+2
__device__ float g_colmax[NB * SEGS * W];
__device__ float g_carry [NB * SEGS * W];

// ---------------------------------------------------------------------------
// K1: fused convA(3x3)+BN+ReLU producing x1, plus segment-local bottom-up
// column cummax; emits i2 only at the 3 lowest-index rows of each 32-row band.
// ---------------------------------------------------------------------------
#define K1_COLS 128
#define K1_CH 16

__global__ __launch_bounds__(K1_COLS) void k1_convA_colscan(
    const float* __restrict__ x,
    const float* __restrict__ wa, const float* __restrict__ pba,
    const float* __restrict__ pga, const float* __restrict__ pbta,
    const float* __restrict__ pma, const float* __restrict__ pva)
{
    __shared__ float xs[K1_CH + 2][K1_COLS + 2];
    const int tid = threadIdx.x;
    const int c0  = blockIdx.x * K1_COLS;
    const int seg = blockIdx.y;
    const int b   = blockIdx.z;
    const int h0  = seg * SEGH;
    const size_t ib = (size_t)b * NPIX;

    float w[9];
#pragma unroll
    for (int i = 0; i < 9; i++) w[i] = __ldg(&wa[i]);
    const float sa = __ldg(pga) * rsqrtf(__ldg(pva) + 1e-5f);
    const float Ba = sa * (__ldg(pba) - __ldg(pma)) + __ldg(pbta);

    float m = 0.0f;
    const int col = c0 + tid;

    for (int k = 0; k < SEGH / K1_CH; k++) {
        const int hb = h0 + SEGH - K1_CH - k * K1_CH;
        __syncthreads();
#pragma unroll
        for (int r = 0; r < K1_CH + 2; r++) {
            int g = hb - 1 + r;
            float v = 0.0f;
            if ((unsigned)g < H) v = __ldg(&x[ib + (size_t)g * W + col]);
            xs[r][tid + 1] = v;
        }
        if (tid < K1_CH + 2) {
            int g = hb - 1 + tid, c = c0 - 1;
            float v = 0.0f;
            if ((unsigned)g < H && c >= 0) v = __ldg(&x[ib + (size_t)g * W + c]);
            xs[tid][0] = v;
        } else if (tid >= 32 && tid < 32 + K1_CH + 2) {
            int g = hb - 1 + (tid - 32), c = c0 + K1_COLS;
            float v = 0.0f;
            if ((unsigned)g < H && c < W) v = __ldg(&x[ib + (size_t)g * W + c]);
            xs[tid - 32][K1_COLS + 1] = v;
        }
        __syncthreads();

        float rA[3], rB[3], rC[3];
#pragma unroll
        for (int kx = 0; kx < 3; kx++) {
            rA[kx] = xs[K1_CH - 1][tid + kx];
            rB[kx] = xs[K1_CH    ][tid + kx];
            rC[kx] = xs[K1_CH + 1][tid + kx];
        }
#pragma unroll
        for (int hh = K1_CH - 1; hh >= 0; hh--) {
            float acc = 0.0f;
#pragma unroll
            for (int kx = 0; kx < 3; kx++) {
                acc = fmaf(w[0 + kx], rA[kx], acc);
                acc = fmaf(w[3 + kx], rB[kx], acc);
                acc = fmaf(w[6 + kx], rC[kx], acc);
            }
            float v = fmaxf(fmaf(sa, acc, Ba), 0.0f);
            m = fmaxf(m, v);
            const int rg = hb + hh;
            g_x1[ib + (size_t)rg * W + col] = v;
            if ((rg & 31) < 3)
                g_i2top[(((size_t)b * 32 + (rg >> 5)) * 3 + (rg & 31)) * W + col] = m;
            if (hh > 0) {
#pragma unroll
                for (int kx = 0; kx < 3; kx++) {
                    rC[kx] = rB[kx];
                    rB[kx] = rA[kx];
                    rA[kx] = xs[hh - 1][tid + kx];
                }
            }
        }
    }
    g_colmax[((size_t)b * SEGS + seg) * W + col] = m;
}

__global__ __launch_bounds__(1024) void k1b_carry()
{
    const int b   = blockIdx.x;
    const int col = threadIdx.x;
    float c = 0.0f;
#pragma unroll
    for (int s = SEGS - 1; s >= 0; s--) {
        size_t o = ((size_t)b * SEGS + s) * W + col;
        g_carry[o] = c;
        c = fmaxf(c, g_colmax[o]);
    }
}

// ---------------------------------------------------------------------------
// K23: bottom-up pencil, full width (256 threads x 4 cols), TWO rows per
// iteration, PROWS=32 band (1024 CTAs), local t-halos, 3 barriers per
// pair-iteration. __launch_bounds__(256,3) to force >=3 CTAs/SM.
// ---------------------------------------------------------------------------
#define PROWS 32
#define WARPS 8

__device__ __forceinline__ float4 contrib6(const float rw[6],
                                           float w0, float w1, float w2)
{
    float4 c;
    c.x = fmaf(w2, rw[2], fmaf(w1, rw[1], w0 * rw[0]));
    c.y = fmaf(w2, rw[3], fmaf(w1, rw[2], w0 * rw[1]));
    c.z = fmaf(w2, rw[4], fmaf(w1, rw[3], w0 * rw[2]));
    c.w = fmaf(w2, rw[5], fmaf(w1, rw[4], w0 * rw[3]));
    return c;
}

__device__ __forceinline__ float4 add4(float4 a, float4 b)
{
    return make_float4(a.x + b.x, a.y + b.y, a.z + b.z, a.w + b.w);
}

__device__ __forceinline__ float4 stage_apply(const float r6[6],
                                              const float wv[9],
                                              float4& Ac, float4& Bc)
{
    float4 cf = contrib6(r6, wv[0], wv[1], wv[2]);
    float4 cm = contrib6(r6, wv[3], wv[4], wv[5]);
    float4 cn = contrib6(r6, wv[6], wv[7], wv[8]);
    float4 raw = add4(Ac, cf);
    Ac = add4(Bc, cm);
    Bc = cn;
    return raw;
}

__device__ __forceinline__ void exchange2(
    float4 vA, float4 vB, float oA[6], float oB[6],
    float* eL, float* eR, int lane, int warp)
{
    float LA = __shfl_up_sync(0xffffffffu, vA.w, 1);
    float RA = __shfl_down_sync(0xffffffffu, vA.x, 1);
    float LB = __shfl_up_sync(0xffffffffu, vB.w, 1);
    float RB = __shfl_down_sync(0xffffffffu, vB.x, 1);
    if (lane == 31) { eL[warp] = vA.w; eL[8 + warp] = vB.w; }
    if (lane == 0)  { eR[warp] = vA.x; eR[8 + warp] = vB.x; }
    __syncthreads();
    if (lane == 0) {
        LA = warp > 0 ? eL[warp - 1] : 0.0f;
        LB = warp > 0 ? eL[8 + warp - 1] : 0.0f;
    }
    if (lane == 31) {
        RA = warp < 7 ? eR[warp + 1] : 0.0f;
        RB = warp < 7 ? eR[8 + warp + 1] : 0.0f;
    }
    oA[0] = LA; oA[1] = vA.x; oA[2] = vA.y; oA[3] = vA.z; oA[4] = vA.w; oA[5] = RA;
    oB[0] = LB; oB[1] = vB.x; oB[2] = vB.y; oB[3] = vB.z; oB[4] = vB.w; oB[5] = RB;
}

__device__ __forceinline__ float4 ldrow4(const float* p, size_t ib, int r, int col0)
{
    if ((unsigned)r < H)
        return *(const float4*)(p + ib + (size_t)r * W + col0);
    return make_float4(0.f, 0.f, 0.f, 0.f);
}

__global__ __launch_bounds__(256, 3) void k23_pencil(
    const float* __restrict__ x,
    const float* __restrict__ wb, const float* __restrict__ pbb,
    const float* __restrict__ pgb, const float* __restrict__ pbtb,
    const float* __restrict__ pmb, const float* __restrict__ pvb,
    const float* __restrict__ pwc, const float* __restrict__ pbc,
    const float* __restrict__ pgc, const float* __restrict__ pbtc,
    const float* __restrict__ pmc, const float* __restrict__ pvc,
    const float* __restrict__ wa, const float* __restrict__ pba,
    const float* __restrict__ pga, const float* __restrict__ pbta,
    const float* __restrict__ pma, const float* __restrict__ pva,
    const float* __restrict__ wd, const float* __restrict__ pbd,
    const float* __restrict__ pwe, const float* __restrict__ pbe,
    float* __restrict__ out)
{
    __shared__ float wtA[WARPS], wtB[WARPS];
    __shared__ float eX1H[WARPS], eX1L[WARPS];
    __shared__ float eI2wH[WARPS], eI2wL[WARPS];
    __shared__ float eI2xH[WARPS], eI2xL[WARPS];
    __shared__ float eSL[16], eSR[16], eUL[16], eUR[16];

    const int tid  = threadIdx.x;
    const int lane = tid & 31;
    const int warp = tid >> 5;
    const int h0   = blockIdx.x * PROWS;
    const int b    = blockIdx.y;
    const size_t ib = (size_t)b * NPIX;
    const int col0 = tid * 4;

    const float sbn = __ldg(pgb) * rsqrtf(__ldg(pvb) + 1e-5f);
    const float Bb  = sbn * (__ldg(pbb) - __ldg(pmb)) + __ldg(pbtb);
    const float scn = __ldg(pgc) * rsqrtf(__ldg(pvc) + 1e-5f);
    const float c2x = __ldg(pwc) * scn;
    const float c2b = scn * (__ldg(pbc) - __ldg(pmc)) + __ldg(pbtc);
    const float san = __ldg(pga) * rsqrtf(__ldg(pva) + 1e-5f);
    const float Ba  = san * (__ldg(pba) - __ldg(pma)) + __ldg(pbta);
    const float bdv = __ldg(pbd);
    const float wev = __ldg(pwe);
    const float bev = __ldg(pbe);
    float wbv[9], wav[9], wdv[9];
#pragma unroll
    for (int i = 0; i < 9; i++) {
        wbv[i] = __ldg(&wb[i]);
        wav[i] = __ldg(&wa[i]);
        wdv[i] = __ldg(&wd[i]);
    }

    const float4 Z4 = make_float4(0.f, 0.f, 0.f, 0.f);
    float4 sAc = Z4, sBc = Z4, uAc = Z4, uBc = Z4, oAc = Z4, oBc = Z4;
    float4 m = Z4;

    const int P = h0 + PROWS;
    const bool warm = P < H;
    float4 cwv = Z4;
    if (warm)
        cwv = *(const float4*)(g_carry + ((size_t)b * SEGS + (P >> 7)) * W + col0);
    const int band = P >> 5;

    float4 p_x1H = ldrow4(g_x1, ib, P + 2, col0);
    float4 p_x1L = ldrow4(g_x1, ib, P + 1, col0);
    float4 p_xH  = ldrow4(x,    ib, P + 3, col0);
    float4 p_xL  = ldrow4(x,    ib, P + 2, col0);

#pragma unroll 1
    for (int it = 0; it < (PROWS + 6) / 2; it++) {
        const int rH = P + 2 - 2 * it;
        const int rL = rH - 1;
        float4 cx1H = p_x1H, cx1L = p_x1L, cxH = p_xH, cxL = p_xL;
        p_x1H = ldrow4(g_x1, ib, rH - 2, col0);
        p_x1L = ldrow4(g_x1, ib, rH - 3, col0);
        p_xH  = ldrow4(x,    ib, rH - 1, col0);
        p_xL  = ldrow4(x,    ib, rH - 2, col0);

        // ---- i2 per column (register; warm-up from i2top+carry) ----
        float4 i2H, i2L;
        if (it == 0) {
            i2H = Z4; i2L = Z4;
            if (warm) {
                float4 v2 = *(const float4*)(g_i2top + (((size_t)b * 32 + band) * 3 + 2) * W + col0);
                float4 v1 = *(const float4*)(g_i2top + (((size_t)b * 32 + band) * 3 + 1) * W + col0);
                i2H.x = fmaxf(v2.x, cwv.x); i2H.y = fmaxf(v2.y, cwv.y);
                i2H.z = fmaxf(v2.z, cwv.z); i2H.w = fmaxf(v2.w, cwv.w);
                i2L.x = fmaxf(v1.x, cwv.x); i2L.y = fmaxf(v1.y, cwv.y);
                i2L.z = fmaxf(v1.z, cwv.z); i2L.w = fmaxf(v1.w, cwv.w);
            }
        } else if (it == 1) {
            i2H = Z4;
            if (warm) {
                float4 v0 = *(const float4*)(g_i2top + (((size_t)b * 32 + band) * 3 + 0) * W + col0);
                i2H.x = fmaxf(v0.x, cwv.x); i2H.y = fmaxf(v0.y, cwv.y);
                i2H.z = fmaxf(v0.z, cwv.z); i2H.w = fmaxf(v0.w, cwv.w);
            }
            m = i2H;
            m.x = fmaxf(m.x, cx1L.x); m.y = fmaxf(m.y, cx1L.y);
            m.z = fmaxf(m.z, cx1L.z); m.w = fmaxf(m.w, cx1L.w);
            i2L = m;
        } else {
            m.x = fmaxf(m.x, cx1H.x); m.y = fmaxf(m.y, cx1H.y);
            m.z = fmaxf(m.z, cx1H.z); m.w = fmaxf(m.w, cx1H.w);
            i2H = m;
            m.x = fmaxf(m.x, cx1L.x); m.y = fmaxf(m.y, cx1L.y);
            m.z = fmaxf(m.z, cx1L.z); m.w = fmaxf(m.w, cx1L.w);
            i2L = m;
        }

        // ---- interleaved row suffix cummax (i1) ----
        float h3 = cx1H.w;
        float h2 = fmaxf(cx1H.z, h3);
        float h1 = fmaxf(cx1H.y, h2);
        float h0s = fmaxf(cx1H.x, h1);
        float l3 = cx1L.w;
        float l2 = fmaxf(cx1L.z, l3);
        float l1 = fmaxf(cx1L.y, l2);
        float l0s = fmaxf(cx1L.x, l1);
        float inH = h0s, inL = l0s;
#pragma unroll
        for (int off = 1; off < 32; off <<= 1) {
            inH = fmaxf(inH, __shfl_down_sync(0xffffffffu, inH, off));
            inL = fmaxf(inL, __shfl_down_sync(0xffffffffu, inL, off));
        }
        float rsH = __shfl_down_sync(0xffffffffu, inH, 1);
        float rsL = __shfl_down_sync(0xffffffffu, inL, 1);
        if (lane == 31) { rsH = 0.0f; rsL = 0.0f; }
        if (lane == 0) {
            wtA[warp] = inH; wtB[warp] = inL;
            eI2xH[warp] = i2H.x; eI2xL[warp] = i2L.x;
        }
        if (lane == 31) {
            eX1H[warp] = cx1H.w; eX1L[warp] = cx1L.w;
            eI2wH[warp] = i2H.w; eI2wL[warp] = i2L.w;
        }
        __syncthreads();                                        // bar 1
#pragma unroll
        for (int w2 = 0; w2 < WARPS; w2++)
            if (w2 > warp) { rsH = fmaxf(rsH, wtA[w2]); rsL = fmaxf(rsL, wtB[w2]); }

        // ---- t values + locally-computed halos (no barrier) ----
        float xwH = __shfl_up_sync(0xffffffffu, cx1H.w, 1);
        float iwH = __shfl_up_sync(0xffffffffu, i2H.w, 1);
        float xwL = __shfl_up_sync(0xffffffffu, cx1L.w, 1);
        float iwL = __shfl_up_sync(0xffffffffu, i2L.w, 1);
        float ixH = __shfl_down_sync(0xffffffffu, i2H.x, 1);
        float ixL = __shfl_down_sync(0xffffffffu, i2L.x, 1);
        if (lane == 0 && warp > 0) {
            xwH = eX1H[warp - 1]; iwH = eI2wH[warp - 1];
            xwL = eX1L[warp - 1]; iwL = eI2wL[warp - 1];
        }
        if (lane == 31 && warp < 7) {
            ixH = eI2xH[warp + 1]; ixL = eI2xL[warp + 1];
        }

        float sufH0 = fmaxf(h0s, rsH);
        float sufL0 = fmaxf(l0s, rsL);
        float t6H[6], t6L[6];
        t6H[1] = sufH0 + i2H.x;          t6L[1] = sufL0 + i2L.x;
        t6H[2] = fmaxf(h1, rsH) + i2H.y; t6L[2] = fmaxf(l1, rsL) + i2L.y;
        t6H[3] = fmaxf(h2, rsH) + i2H.z; t6L[3] = fmaxf(l2, rsL) + i2L.z;
        t6H[4] = fmaxf(h3, rsH) + i2H.w; t6L[4] = fmaxf(l3, rsL) + i2L.w;
        t6H[0] = fmaxf(xwH, sufH0) + iwH;
        t6L[0] = fmaxf(xwL, sufL0) + iwL;
        t6H[5] = rsH + ixH;
        t6L[5] = rsL + ixL;
        if (tid == 0)   { t6H[0] = 0.0f; t6L[0] = 0.0f; }
        if (tid == 255) { t6H[5] = 0.0f; t6L[5] = 0.0f; }
        if (rH < 0) {
#pragma unroll
            for (int j = 0; j < 6; j++) t6H[j] = 0.0f;
        }
        if (rL < 0) {
#pragma unroll
            for (int j = 0; j < 6; j++) t6L[j] = 0.0f;
        }

        // ---- s stage: completes rows rH+1, rH ----
        float4 srawH = stage_apply(t6H, wbv, sAc, sBc);
        float4 srawL = stage_apply(t6L, wbv, sAc, sBc);
        const int sH = rH + 1, sL = rH;
        const bool svH = ((unsigned)sH < H) && (sH >= h0 - 2) && (sH <= h0 + PROWS + 1);
        const bool svL = ((unsigned)sL < H) && (sL >= h0 - 2) && (sL <= h0 + PROWS + 1);
        float4 svalH, svalL;
        svalH.x = svH ? fmaxf(fmaf(sbn, srawH.x, Bb) + fmaf(c2x, cxH.x, c2b), 0.f) : 0.f;
        svalH.y = svH ? fmaxf(fmaf(sbn, srawH.y, Bb) + fmaf(c2x, cxH.y, c2b), 0.f) : 0.f;
        svalH.z = svH ? fmaxf(fmaf(sbn, srawH.z, Bb) + fmaf(c2x, cxH.z, c2b), 0.f) : 0.f;
        svalH.w = svH ? fmaxf(fmaf(sbn, srawH.w, Bb) + fmaf(c2x, cxH.w, c2b), 0.f) : 0.f;
        svalL.x = svL ? fmaxf(fmaf(sbn, srawL.x, Bb) + fmaf(c2x, cxL.x, c2b), 0.f) : 0.f;
        svalL.y = svL ? fmaxf(fmaf(sbn, srawL.y, Bb) + fmaf(c2x, cxL.y, c2b), 0.f) : 0.f;
        svalL.z = svL ? fmaxf(fmaf(sbn, srawL.z, Bb) + fmaf(c2x, cxL.z, c2b), 0.f) : 0.f;
        svalL.w = svL ? fmaxf(fmaf(sbn, srawL.w, Bb) + fmaf(c2x, cxL.w, c2b), 0.f) : 0.f;

        float s6H[6], s6L[6];
        exchange2(svalH, svalL, s6H, s6L, eSL, eSR, lane, warp); // bar 2

        // ---- u stage: completes rows rH+2, rH+1 ----
        float4 urawH = stage_apply(s6H, wav, uAc, uBc);
        float4 urawL = stage_apply(s6L, wav, uAc, uBc);
        const int uH = rH + 2, uL = rH + 1;
        const bool uvH = ((unsigned)uH < H) && (uH >= h0 - 1) && (uH <= h0 + PROWS);
        const bool uvL = ((unsigned)uL < H) && (uL >= h0 - 1) && (uL <= h0 + PROWS);
        float4 uvalH, uvalL;
        uvalH.x = uvH ? fmaxf(fmaf(san, urawH.x, Ba), 0.f) : 0.f;
        uvalH.y = uvH ? fmaxf(fmaf(san, urawH.y, Ba), 0.f) : 0.f;
        uvalH.z = uvH ? fmaxf(fmaf(san, urawH.z, Ba), 0.f) : 0.f;
        uvalH.w = uvH ? fmaxf(fmaf(san, urawH.w, Ba), 0.f) : 0.f;
        uvalL.x = uvL ? fmaxf(fmaf(san, urawL.x, Ba), 0.f) : 0.f;
        uvalL.y = uvL ? fmaxf(fmaf(san, urawL.y, Ba), 0.f) : 0.f;
        uvalL.z = uvL ? fmaxf(fmaf(san, urawL.z, Ba), 0.f) : 0.f;
        uvalL.w = uvL ? fmaxf(fmaf(san, urawL.w, Ba), 0.f) : 0.f;

        float u6H[6], u6L[6];
        exchange2(uvalH, uvalL, u6H, u6L, eUL, eUR, lane, warp); // bar 3

        // ---- out stage: completes rows rH+3, rH+2 ----
        float4 orawH = stage_apply(u6H, wdv, oAc, oBc);
        float4 orawL = stage_apply(u6L, wdv, oAc, oBc);
        const int oH = rH + 3, oL = rH + 2;
        if (oH >= h0 && oH < h0 + PROWS) {
            float4 ov;
            ov.x = fmaf(wev, fmaxf(orawH.x + bdv, 0.f), bev);
            ov.y = fmaf(wev, fmaxf(orawH.y + bdv, 0.f), bev);
            ov.z = fmaf(wev, fmaxf(orawH.z + bdv, 0.f), bev);
            ov.w = fmaf(wev, fmaxf(orawH.w + bdv, 0.f), bev);
            *(float4*)(out + ib + (size_t)oH * W + col0) = ov;
        }
        if (oL >= h0 && oL < h0 + PROWS) {
            float4 ov;
            ov.x = fmaf(wev, fmaxf(orawL.x + bdv, 0.f), bev);
            ov.y = fmaf(wev, fmaxf(orawL.y + bdv, 0.f), bev);
            ov.z = fmaf(wev, fmaxf(orawL.z + bdv, 0.f), bev);
            ov.w = fmaf(wev, fmaxf(orawL.w + bdv, 0.f), bev);
            *(float4*)(out + ib + (size_t)oL * W + col0) = ov;
        }
    }
}

// ---------------------------------------------------------------------------
extern "C" void kernel_launch(void* const* d_in, const int* in_sizes, int n_in,
                              void* d_out, int out_size)
{
    const float* x   = (const float*)d_in[0];
    const float* wa  = (const float*)d_in[1];
    const float* ba  = (const float*)d_in[2];
    const float* ga  = (const float*)d_in[3];
    const float* bta = (const float*)d_in[4];
    const float* ma  = (const float*)d_in[5];
    const float* va  = (const float*)d_in[6];
    const float* wb  = (const float*)d_in[7];
    const float* bb  = (const float*)d_in[8];
    const float* gb  = (const float*)d_in[9];
    const float* btb = (const float*)d_in[10];
    const float* mb  = (const float*)d_in[11];
    const float* vb  = (const float*)d_in[12];
    const float* wc  = (const float*)d_in[13];
    const float* bc  = (const float*)d_in[14];
    const float* gc  = (const float*)d_in[15];
    const float* btc = (const float*)d_in[16];
    const float* mc  = (const float*)d_in[17];
    const float* vc  = (const float*)d_in[18];
    const float* wd  = (const float*)d_in[19];
    const float* bd  = (const float*)d_in[20];
    const float* we  = (const float*)d_in[21];
    const float* be  = (const float*)d_in[22];
    float* out = (float*)d_out;

    dim3 g1(W / K1_COLS, SEGS, NB);
    k1_convA_colscan<<<g1, K1_COLS>>>(x, wa, ba, ga, bta, ma, va);

    k1b_carry<<<NB, 1024>>>();

    dim3 g23(H / PROWS, NB);
    k23_pencil<<<g23, 256>>>(
        x,
        wb, bb, gb, btb, mb, vb,
        wc, bc, gc, btc, mc, vc,
        wa, ba, ga, bta, ma, va,
        wd, bd, we, be,
        out);
}

// round 15
// speedup vs baseline: 1.0130x; 1.0130x over previous
#include <cuda_runtime.h>
#include <math.h>

#define H 1024
#define W 1024
#define NB 32
#define NPIX (1024*1024)
#define SEGS 8
#define SEGH 128

// Scratch (allocation is forbidden; use device globals)
__device__ float g_x1[33554432];
__device__ float g_i2top[NB * 32 * 3 * W];   // seg-local i2 at rows 32k..32k+2
__device__ float g_colmax[NB * SEGS * W];

// ---------------------------------------------------------------------------
// K1: fused convA(3x3)+BN+ReLU producing x1, plus segment-local bottom-up
// column cummax; emits i2 only at the 3 lowest-index rows of each 32-row band.
// Chunk-rolling: halo rows carried in registers across chunks (CH loads/chunk).
// ---------------------------------------------------------------------------
#define K1_COLS 128
#define K1_CH 16

__global__ __launch_bounds__(K1_COLS) void k1_convA_colscan(
    const float* __restrict__ x,
    const float* __restrict__ wa, const float* __restrict__ pba,
    const float* __restrict__ pga, const float* __restrict__ pbta,
    const float* __restrict__ pma, const float* __restrict__ pva)
{
    __shared__ float xs[K1_CH + 2][K1_COLS + 2];
    const int tid = threadIdx.x;
    const int c0  = blockIdx.x * K1_COLS;
    const int seg = blockIdx.y;
    const int b   = blockIdx.z;
    const int h0  = seg * SEGH;
    const size_t ib = (size_t)b * NPIX;

    float w[9];
#pragma unroll
    for (int i = 0; i < 9; i++) w[i] = __ldg(&wa[i]);
    const float sa = __ldg(pga) * rsqrtf(__ldg(pva) + 1e-5f);
    const float Ba = sa * (__ldg(pba) - __ldg(pma)) + __ldg(pbta);

    float m = 0.0f;
    const int col = c0 + tid;
    float rA[3], rB[3], rC[3];

    for (int k = 0; k < SEGH / K1_CH; k++) {
        const int hb = h0 + SEGH - K1_CH - k * K1_CH;
        const int nrows = (k == 0) ? (K1_CH + 2) : K1_CH;   // halo kept in regs
        __syncthreads();
#pragma unroll
        for (int r = 0; r < K1_CH + 2; r++) {
            if (r < nrows) {
                int g = hb - 1 + r;
                float v = 0.0f;
                if ((unsigned)g < H) v = __ldg(&x[ib + (size_t)g * W + col]);
                xs[r][tid + 1] = v;
            }
        }
        if (tid < K1_CH + 2) {
            if (tid < nrows) {
                int g = hb - 1 + tid, c = c0 - 1;
                float v = 0.0f;
                if ((unsigned)g < H && c >= 0) v = __ldg(&x[ib + (size_t)g * W + c]);
                xs[tid][0] = v;
            }
        } else if (tid >= 32 && tid < 32 + K1_CH + 2) {
            int r = tid - 32;
            if (r < nrows) {
                int g = hb - 1 + r, c = c0 + K1_COLS;
                float v = 0.0f;
                if ((unsigned)g < H && c < W) v = __ldg(&x[ib + (size_t)g * W + c]);
                xs[r][K1_COLS + 1] = v;
            }
        }
        __syncthreads();

        if (k == 0) {
#pragma unroll
            for (int kx = 0; kx < 3; kx++) {
                rA[kx] = xs[K1_CH - 1][tid + kx];
                rB[kx] = xs[K1_CH    ][tid + kx];
                rC[kx] = xs[K1_CH + 1][tid + kx];
            }
        } else {
            // rA,rB from previous chunk hold rows hb+CH-1, hb+CH (windows)
#pragma unroll
            for (int kx = 0; kx < 3; kx++) {
                rC[kx] = rB[kx];
                rB[kx] = rA[kx];
                rA[kx] = xs[K1_CH - 1][tid + kx];   // row hb+CH-2
            }
        }
#pragma unroll
        for (int hh = K1_CH - 1; hh >= 0; hh--) {
            float acc = 0.0f;
#pragma unroll
            for (int kx = 0; kx < 3; kx++) {
                acc = fmaf(w[0 + kx], rA[kx], acc);
                acc = fmaf(w[3 + kx], rB[kx], acc);
                acc = fmaf(w[6 + kx], rC[kx], acc);
            }
            float v = fmaxf(fmaf(sa, acc, Ba), 0.0f);
            m = fmaxf(m, v);
            const int rg = hb + hh;
            g_x1[ib + (size_t)rg * W + col] = v;
            if ((rg & 31) < 3)
                g_i2top[(((size_t)b * 32 + (rg >> 5)) * 3 + (rg & 31)) * W + col] = m;
            if (hh > 0) {
#pragma unroll
                for (int kx = 0; kx < 3; kx++) {
                    rC[kx] = rB[kx];
                    rB[kx] = rA[kx];
                    rA[kx] = xs[hh - 1][tid + kx];
                }
            }
        }
    }
    g_colmax[((size_t)b * SEGS + seg) * W + col] = m;
}

// ---------------------------------------------------------------------------
// K23: bottom-up pencil, full width (256 threads x 4 cols), TWO rows per
// iteration, PROWS=32 band (1024 CTAs), local t-halos, 3 barriers per
// pair-iteration. Carry computed inline from g_colmax (k1b kernel fused away).
// ---------------------------------------------------------------------------
#define PROWS 32
#define WARPS 8

__device__ __forceinline__ float4 contrib6(const float rw[6],
                                           float w0, float w1, float w2)
{
    float4 c;
    c.x = fmaf(w2, rw[2], fmaf(w1, rw[1], w0 * rw[0]));
    c.y = fmaf(w2, rw[3], fmaf(w1, rw[2], w0 * rw[1]));
    c.z = fmaf(w2, rw[4], fmaf(w1, rw[3], w0 * rw[2]));
    c.w = fmaf(w2, rw[5], fmaf(w1, rw[4], w0 * rw[3]));
    return c;
}

__device__ __forceinline__ float4 add4(float4 a, float4 b)
{
    return make_float4(a.x + b.x, a.y + b.y, a.z + b.z, a.w + b.w);
}

__device__ __forceinline__ float4 stage_apply(const float r6[6],
                                              const float wv[9],
                                              float4& Ac, float4& Bc)
{
    float4 cf = contrib6(r6, wv[0], wv[1], wv[2]);
    float4 cm = contrib6(r6, wv[3], wv[4], wv[5]);
    float4 cn = contrib6(r6, wv[6], wv[7], wv[8]);
    float4 raw = add4(Ac, cf);
    Ac = add4(Bc, cm);
    Bc = cn;
    return raw;
}

__device__ __forceinline__ void exchange2(
    float4 vA, float4 vB, float oA[6], float oB[6],
    float* eL, float* eR, int lane, int warp)
{
    float LA = __shfl_up_sync(0xffffffffu, vA.w, 1);
    float RA = __shfl_down_sync(0xffffffffu, vA.x, 1);
    float LB = __shfl_up_sync(0xffffffffu, vB.w, 1);
    float RB = __shfl_down_sync(0xffffffffu, vB.x, 1);
    if (lane == 31) { eL[warp] = vA.w; eL[8 + warp] = vB.w; }
    if (lane == 0)  { eR[warp] = vA.x; eR[8 + warp] = vB.x; }
    __syncthreads();
    if (lane == 0) {
        LA = warp > 0 ? eL[warp - 1] : 0.0f;
        LB = warp > 0 ? eL[8 + warp - 1] : 0.0f;
    }
    if (lane == 31) {
        RA = warp < 7 ? eR[warp + 1] : 0.0f;
        RB = warp < 7 ? eR[8 + warp + 1] : 0.0f;
    }
    oA[0] = LA; oA[1] = vA.x; oA[2] = vA.y; oA[3] = vA.z; oA[4] = vA.w; oA[5] = RA;
    oB[0] = LB; oB[1] = vB.x; oB[2] = vB.y; oB[3] = vB.z; oB[4] = vB.w; oB[5] = RB;
}

__device__ __forceinline__ float4 ldrow4(const float* p, size_t ib, int r, int col0)
{
    if ((unsigned)r < H)
        return *(const float4*)(p + ib + (size_t)r * W + col0);
    return make_float4(0.f, 0.f, 0.f, 0.f);
}

__global__ __launch_bounds__(256, 3) void k23_pencil(
    const float* __restrict__ x,
    const float* __restrict__ wb, const float* __restrict__ pbb,
    const float* __restrict__ pgb, const float* __restrict__ pbtb,
    const float* __restrict__ pmb, const float* __restrict__ pvb,
    const float* __restrict__ pwc, const float* __restrict__ pbc,
    const float* __restrict__ pgc, const float* __restrict__ pbtc,
    const float* __restrict__ pmc, const float* __restrict__ pvc,
    const float* __restrict__ wa, const float* __restrict__ pba,
    const float* __restrict__ pga, const float* __restrict__ pbta,
    const float* __restrict__ pma, const float* __restrict__ pva,
    const float* __restrict__ wd, const float* __restrict__ pbd,
    const float* __restrict__ pwe, const float* __restrict__ pbe,
    float* __restrict__ out)
{
    __shared__ float wtA[WARPS], wtB[WARPS];
    __shared__ float eX1H[WARPS], eX1L[WARPS];
    __shared__ float eI2wH[WARPS], eI2wL[WARPS];
    __shared__ float eI2xH[WARPS], eI2xL[WARPS];
    __shared__ float eSL[16], eSR[16], eUL[16], eUR[16];

    const int tid  = threadIdx.x;
    const int lane = tid & 31;
    const int warp = tid >> 5;
    const int h0   = blockIdx.x * PROWS;
    const int b    = blockIdx.y;
    const size_t ib = (size_t)b * NPIX;
    const int col0 = tid * 4;

    const float sbn = __ldg(pgb) * rsqrtf(__ldg(pvb) + 1e-5f);
    const float Bb  = sbn * (__ldg(pbb) - __ldg(pmb)) + __ldg(pbtb);
    const float scn = __ldg(pgc) * rsqrtf(__ldg(pvc) + 1e-5f);
    const float c2x = __ldg(pwc) * scn;
    const float c2b = scn * (__ldg(pbc) - __ldg(pmc)) + __ldg(pbtc);
    const float san = __ldg(pga) * rsqrtf(__ldg(pva) + 1e-5f);
    const float Ba  = san * (__ldg(pba) - __ldg(pma)) + __ldg(pbta);
    const float bdv = __ldg(pbd);
    const float wev = __ldg(pwe);
    const float bev = __ldg(pbe);
    float wbv[9], wav[9], wdv[9];
#pragma unroll
    for (int i = 0; i < 9; i++) {
        wbv[i] = __ldg(&wb[i]);
        wav[i] = __ldg(&wa[i]);
        wdv[i] = __ldg(&wd[i]);
    }

    const float4 Z4 = make_float4(0.f, 0.f, 0.f, 0.f);
    float4 sAc = Z4, sBc = Z4, uAc = Z4, uBc = Z4, oAc = Z4, oBc = Z4;
    float4 m = Z4;

    const int P = h0 + PROWS;
    const bool warm = P < H;
    // carry for this band's segment, computed inline (fused k1b):
    // carry[seg] = max over colmax[s] for s > seg
    float4 cwv = Z4;
    if (warm) {
        const int segP = P >> 7;
#pragma unroll 1
        for (int s = segP + 1; s < SEGS; s++) {
            float4 v = *(const float4*)(g_colmax + ((size_t)b * SEGS + s) * W + col0);
            cwv.x = fmaxf(cwv.x, v.x); cwv.y = fmaxf(cwv.y, v.y);
            cwv.z = fmaxf(cwv.z, v.z); cwv.w = fmaxf(cwv.w, v.w);
        }
    }
    const int band = P >> 5;

    float4 p_x1H = ldrow4(g_x1, ib, P + 2, col0);
    float4 p_x1L = ldrow4(g_x1, ib, P + 1, col0);
    float4 p_xH  = ldrow4(x,    ib, P + 3, col0);
    float4 p_xL  = ldrow4(x,    ib, P + 2, col0);

#pragma unroll 1
    for (int it = 0; it < (PROWS + 6) / 2; it++) {
        const int rH = P + 2 - 2 * it;
        const int rL = rH - 1;
        float4 cx1H = p_x1H, cx1L = p_x1L, cxH = p_xH, cxL = p_xL;
        p_x1H = ldrow4(g_x1, ib, rH - 2, col0);
        p_x1L = ldrow4(g_x1, ib, rH - 3, col0);
        p_xH  = ldrow4(x,    ib, rH - 1, col0);
        p_xL  = ldrow4(x,    ib, rH - 2, col0);

        // ---- i2 per column (register; warm-up from i2top+carry) ----
        float4 i2H, i2L;
        if (it == 0) {
            i2H = Z4; i2L = Z4;
            if (warm) {
                float4 v2 = *(const float4*)(g_i2top + (((size_t)b * 32 + band) * 3 + 2) * W + col0);
                float4 v1 = *(const float4*)(g_i2top + (((size_t)b * 32 + band) * 3 + 1) * W + col0);
                i2H.x = fmaxf(v2.x, cwv.x); i2H.y = fmaxf(v2.y, cwv.y);
                i2H.z = fmaxf(v2.z, cwv.z); i2H.w = fmaxf(v2.w, cwv.w);
                i2L.x = fmaxf(v1.x, cwv.x); i2L.y = fmaxf(v1.y, cwv.y);
                i2L.z = fmaxf(v1.z, cwv.z); i2L.w = fmaxf(v1.w, cwv.w);
            }
        } else if (it == 1) {
            i2H = Z4;
            if (warm) {
                float4 v0 = *(const float4*)(g_i2top + (((size_t)b * 32 + band) * 3 + 0) * W + col0);
                i2H.x = fmaxf(v0.x, cwv.x); i2H.y = fmaxf(v0.y, cwv.y);
                i2H.z = fmaxf(v0.z, cwv.z); i2H.w = fmaxf(v0.w, cwv.w);
            }
            m = i2H;
            m.x = fmaxf(m.x, cx1L.x); m.y = fmaxf(m.y, cx1L.y);
            m.z = fmaxf(m.z, cx1L.z); m.w = fmaxf(m.w, cx1L.w);
            i2L = m;
        } else {
            m.x = fmaxf(m.x, cx1H.x); m.y = fmaxf(m.y, cx1H.y);
            m.z = fmaxf(m.z, cx1H.z); m.w = fmaxf(m.w, cx1H.w);
            i2H = m;
            m.x = fmaxf(m.x, cx1L.x); m.y = fmaxf(m.y, cx1L.y);
            m.z = fmaxf(m.z, cx1L.z); m.w = fmaxf(m.w, cx1L.w);
            i2L = m;
        }

        // ---- interleaved row suffix cummax (i1) ----
        float h3 = cx1H.w;
        float h2 = fmaxf(cx1H.z, h3);
        float h1 = fmaxf(cx1H.y, h2);
        float h0s = fmaxf(cx1H.x, h1);
        float l3 = cx1L.w;
        float l2 = fmaxf(cx1L.z, l3);
        float l1 = fmaxf(cx1L.y, l2);
        float l0s = fmaxf(cx1L.x, l1);
        float inH = h0s, inL = l0s;
#pragma unroll
        for (int off = 1; off < 32; off <<= 1) {
            inH = fmaxf(inH, __shfl_down_sync(0xffffffffu, inH, off));
            inL = fmaxf(inL, __shfl_down_sync(0xffffffffu, inL, off));
        }
        float rsH = __shfl_down_sync(0xffffffffu, inH, 1);
        float rsL = __shfl_down_sync(0xffffffffu, inL, 1);
        if (lane == 31) { rsH = 0.0f; rsL = 0.0f; }
        if (lane == 0) {
            wtA[warp] = inH; wtB[warp] = inL;
            eI2xH[warp] = i2H.x; eI2xL[warp] = i2L.x;
        }
        if (lane == 31) {
            eX1H[warp] = cx1H.w; eX1L[warp] = cx1L.w;
            eI2wH[warp] = i2H.w; eI2wL[warp] = i2L.w;
        }
        __syncthreads();                                        // bar 1
#pragma unroll
        for (int w2 = 0; w2 < WARPS; w2++)
            if (w2 > warp) { rsH = fmaxf(rsH, wtA[w2]); rsL = fmaxf(rsL, wtB[w2]); }

        // ---- t values + locally-computed halos (no barrier) ----
        float xwH = __shfl_up_sync(0xffffffffu, cx1H.w, 1);
        float iwH = __shfl_up_sync(0xffffffffu, i2H.w, 1);
        float xwL = __shfl_up_sync(0xffffffffu, cx1L.w, 1);
        float iwL = __shfl_up_sync(0xffffffffu, i2L.w, 1);
        float ixH = __shfl_down_sync(0xffffffffu, i2H.x, 1);
        float ixL = __shfl_down_sync(0xffffffffu, i2L.x, 1);
        if (lane == 0 && warp > 0) {
            xwH = eX1H[warp - 1]; iwH = eI2wH[warp - 1];
            xwL = eX1L[warp - 1]; iwL = eI2wL[warp - 1];
        }
        if (lane == 31 && warp < 7) {
            ixH = eI2xH[warp + 1]; ixL = eI2xL[warp + 1];
        }

        float sufH0 = fmaxf(h0s, rsH);
        float sufL0 = fmaxf(l0s, rsL);
        float t6H[6], t6L[6];
        t6H[1] = sufH0 + i2H.x;          t6L[1] = sufL0 + i2L.x;
        t6H[2] = fmaxf(h1, rsH) + i2H.y; t6L[2] = fmaxf(l1, rsL) + i2L.y;
        t6H[3] = fmaxf(h2, rsH) + i2H.z; t6L[3] = fmaxf(l2, rsL) + i2L.z;
        t6H[4] = fmaxf(h3, rsH) + i2H.w; t6L[4] = fmaxf(l3, rsL) + i2L.w;
        t6H[0] = fmaxf(xwH, sufH0) + iwH;
        t6L[0] = fmaxf(xwL, sufL0) + iwL;
        t6H[5] = rsH + ixH;
        t6L[5] = rsL + ixL;
        if (tid == 0)   { t6H[0] = 0.0f; t6L[0] = 0.0f; }
        if (tid == 255) { t6H[5] = 0.0f; t6L[5] = 0.0f; }
        if (rH < 0) {
#pragma unroll
            for (int j = 0; j < 6; j++) t6H[j] = 0.0f;
        }
        if (rL < 0) {
#pragma unroll
            for (int j = 0; j < 6; j++) t6L[j] = 0.0f;
        }

        // ---- s stage: completes rows rH+1, rH ----
        float4 srawH = stage_apply(t6H, wbv, sAc, sBc);
        float4 srawL = stage_apply(t6L, wbv, sAc, sBc);
        const int sH = rH + 1, sL = rH;
        const bool svH = ((unsigned)sH < H) && (sH >= h0 - 2) && (sH <= h0 + PROWS + 1);
        const bool svL = ((unsigned)sL < H) && (sL >= h0 - 2) && (sL <= h0 + PROWS + 1);
        float4 svalH, svalL;
        svalH.x = svH ? fmaxf(fmaf(sbn, srawH.x, Bb) + fmaf(c2x, cxH.x, c2b), 0.f) : 0.f;
        svalH.y = svH ? fmaxf(fmaf(sbn, srawH.y, Bb) + fmaf(c2x, cxH.y, c2b), 0.f) : 0.f;
        svalH.z = svH ? fmaxf(fmaf(sbn, srawH.z, Bb) + fmaf(c2x, cxH.z, c2b), 0.f) : 0.f;
        svalH.w = svH ? fmaxf(fmaf(sbn, srawH.w, Bb) + fmaf(c2x, cxH.w, c2b), 0.f) : 0.f;
        svalL.x = svL ? fmaxf(fmaf(sbn, srawL.x, Bb) + fmaf(c2x, cxL.x, c2b), 0.f) : 0.f;
        svalL.y = svL ? fmaxf(fmaf(sbn, srawL.y, Bb) + fmaf(c2x, cxL.y, c2b), 0.f) : 0.f;
        svalL.z = svL ? fmaxf(fmaf(sbn, srawL.z, Bb) + fmaf(c2x, cxL.z, c2b), 0.f) : 0.f;
        svalL.w = svL ? fmaxf(fmaf(sbn, srawL.w, Bb) + fmaf(c2x, cxL.w, c2b), 0.f) : 0.f;

        float s6H[6], s6L[6];
        exchange2(svalH, svalL, s6H, s6L, eSL, eSR, lane, warp); // bar 2

        // ---- u stage: completes rows rH+2, rH+1 ----
        float4 urawH = stage_apply(s6H, wav, uAc, uBc);
        float4 urawL = stage_apply(s6L, wav, uAc, uBc);
        const int uH = rH + 2, uL = rH + 1;
        const bool uvH = ((unsigned)uH < H) && (uH >= h0 - 1) && (uH <= h0 + PROWS);
        const bool uvL = ((unsigned)uL < H) && (uL >= h0 - 1) && (uL <= h0 + PROWS);
        float4 uvalH, uvalL;
        uvalH.x = uvH ? fmaxf(fmaf(san, urawH.x, Ba), 0.f) : 0.f;
        uvalH.y = uvH ? fmaxf(fmaf(san, urawH.y, Ba), 0.f) : 0.f;
        uvalH.z = uvH ? fmaxf(fmaf(san, urawH.z, Ba), 0.f) : 0.f;
        uvalH.w = uvH ? fmaxf(fmaf(san, urawH.w, Ba), 0.f) : 0.f;
        uvalL.x = uvL ? fmaxf(fmaf(san, urawL.x, Ba), 0.f) : 0.f;
        uvalL.y = uvL ? fmaxf(fmaf(san, urawL.y, Ba), 0.f) : 0.f;
        uvalL.z = uvL ? fmaxf(fmaf(san, urawL.z, Ba), 0.f) : 0.f;
        uvalL.w = uvL ? fmaxf(fmaf(san, urawL.w, Ba), 0.f) : 0.f;

        float u6H[6], u6L[6];
        exchange2(uvalH, uvalL, u6H, u6L, eUL, eUR, lane, warp); // bar 3

        // ---- out stage: completes rows rH+3, rH+2 ----
        float4 orawH = stage_apply(u6H, wdv, oAc, oBc);
        float4 orawL = stage_apply(u6L, wdv, oAc, oBc);
        const int oH = rH + 3, oL = rH + 2;
        if (oH >= h0 && oH < h0 + PROWS) {
            float4 ov;
            ov.x = fmaf(wev, fmaxf(orawH.x + bdv, 0.f), bev);
            ov.y = fmaf(wev, fmaxf(orawH.y + bdv, 0.f), bev);
            ov.z = fmaf(wev, fmaxf(orawH.z + bdv, 0.f), bev);
            ov.w = fmaf(wev, fmaxf(orawH.w + bdv, 0.f), bev);
            *(float4*)(out + ib + (size_t)oH * W + col0) = ov;
        }
        if (oL >= h0 && oL < h0 + PROWS) {
            float4 ov;
            ov.x = fmaf(wev, fmaxf(orawL.x + bdv, 0.f), bev);
            ov.y = fmaf(wev, fmaxf(orawL.y + bdv, 0.f), bev);
            ov.z = fmaf(wev, fmaxf(orawL.z + bdv, 0.f), bev);
            ov.w = fmaf(wev, fmaxf(orawL.w + bdv, 0.f), bev);
            *(float4*)(out + ib + (size_t)oL * W + col0) = ov;
        }
    }
}

// ---------------------------------------------------------------------------
extern "C" void kernel_launch(void* const* d_in, const int* in_sizes, int n_in,
                              void* d_out, int out_size)
{
    const float* x   = (const float*)d_in[0];
    const float* wa  = (const float*)d_in[1];
    const float* ba  = (const float*)d_in[2];
    const float* ga  = (const float*)d_in[3];
    const float* bta = (const float*)d_in[4];
    const float* ma  = (const float*)d_in[5];
    const float* va  = (const float*)d_in[6];
    const float* wb  = (const float*)d_in[7];
    const float* bb  = (const float*)d_in[8];
    const float* gb  = (const float*)d_in[9];
    const float* btb = (const float*)d_in[10];
    const float* mb  = (const float*)d_in[11];
    const float* vb  = (const float*)d_in[12];
    const float* wc  = (const float*)d_in[13];
    const float* bc  = (const float*)d_in[14];
    const float* gc  = (const float*)d_in[15];
    const float* btc = (const float*)d_in[16];
    const float* mc  = (const float*)d_in[17];
    const float* vc  = (const float*)d_in[18];
    const float* wd  = (const float*)d_in[19];
    const float* bd  = (const float*)d_in[20];
    const float* we  = (const float*)d_in[21];
    const float* be  = (const float*)d_in[22];
    float* out = (float*)d_out;

    dim3 g1(W / K1_COLS, SEGS, NB);
    k1_convA_colscan<<<g1, K1_COLS>>>(x, wa, ba, ga, bta, ma, va);

    dim3 g23(H / PROWS, NB);
    k23_pencil<<<g23, 256>>>(
        x,
        wb, bb, gb, btb, mb, vb,
        wc, bc, gc, btc, mc, vc,
        wa, ba, ga, bta, ma, va,
        wd, bd, we, be,
        out);
}